// round 16
// baseline (speedup 1.0000x reference)
#include <cuda_runtime.h>
#include <cstdint>
#include <cstddef>

#define L  27
#define D  64
#define H  8
#define NT 512
#define FULLMASK 0xffffffffu

typedef unsigned long long u64;

__device__ __forceinline__ u64 pk2(float lo, float hi) {
    u64 r; asm("mov.b64 %0,{%1,%2};" : "=l"(r) : "f"(lo), "f"(hi)); return r;
}
__device__ __forceinline__ void upk2(u64 v, float& lo, float& hi) {
    asm("mov.b64 {%0,%1},%2;" : "=f"(lo), "=f"(hi) : "l"(v));
}
__device__ __forceinline__ void fma2(u64& d, u64 a, u64 b) {
    asm("fma.rn.f32x2 %0,%1,%2,%0;" : "+l"(d) : "l"(a), "l"(b));
}
__device__ __forceinline__ u64 mul2(u64 a, u64 b) {
    u64 r; asm("mul.rn.f32x2 %0,%1,%2;" : "=l"(r) : "l"(a), "l"(b)); return r;
}
__device__ __forceinline__ u64 add2(u64 a, u64 b) {
    u64 r; asm("add.rn.f32x2 %0,%1,%2;" : "=l"(r) : "l"(a), "l"(b)); return r;
}

// ---- shared memory layout (float offsets), total 22868 floats = 91472 B ----
// X region (14336 floats), time-multiplexed:
//   phase1: FOUR head slots of 3584 (Q[27][64]=1728, KT4[16][29] float4 = 1856)
//   conv  : Z0[p][m][o] at X[0..5832), Z1 at X[5832..11664)
//   linear: Z = Z0+Z1 pre-reduced into X[0..5832); V heads 4..7 staged X[6912..13824)
//   phase4: V for all 8 heads at X[0..13824)
// CW and G dedicated (CW staged once at kernel start).
#define OFF_X   0
#define OFF_A   14336                // A[8][27][27] = 5832
#define OFF_WT  (OFF_A + 5832)       // 729
#define OFF_BB  (OFF_WT + 729)       // 27
#define OFF_CW  (OFF_BB + 27)        // CW[c][t][o] = 1728 (16B aligned)
#define OFF_G   (OFF_CW + 1728)      // G[p][o] = 216
#define SMEM_FLOATS (OFF_G + 216)    // 22868

__global__ __launch_bounds__(NT, 2)
void attn2_kernel(const float* __restrict__ q, const float* __restrict__ k,
                  const float* __restrict__ v, const float* __restrict__ attn_pre,
                  const float* __restrict__ lin_w, const float* __restrict__ lin_b,
                  const float* __restrict__ conv_w,
                  float* __restrict__ out, float* __restrict__ attn_out)
{
    extern __shared__ float sm[];
    float* X  = sm + OFF_X;
    float* A  = sm + OFF_A;
    float* WT = sm + OFF_WT;
    float* BB = sm + OFF_BB;
    float* CW = sm + OFF_CW;
    float* G  = sm + OFF_G;

    const int b    = blockIdx.x;
    const int tid  = threadIdx.x;
    const int lane = tid & 31;
    const int w    = tid >> 5;       // 0..15
    const int bh0  = b * H;

    // ---------- stage linear + conv weights once, up front ----------
    for (int idx = tid; idx < L * L; idx += NT) {
        int jj = idx / L, mm = idx - jj * L;
        WT[mm * L + jj] = lin_w[idx];              // WT[m][j] = lin_w[j][m]
    }
    if (tid < L) BB[tid] = lin_b[tid];
    for (int idx = tid; idx < H * H * L; idx += NT) {
        int o = idx / (H * L);
        int r = idx - o * (H * L);
        int c = r / L, t = r - c * L;
        CW[(c * L + t) * H + o] = conv_w[idx];     // OIHW, kw==1
    }

    // ---------- phase 1: A = 0.5*attn_pre + 0.0625*QK^T (lower tri, 0 above) ----------
    // 4 heads per pass; 4 warps per head; ~7 rows per warp.
    // K column load predicated by j <= jmax (lanes above the warp's top row only
    // produce discarded upper-triangle values) -> smaller LDS transactions.
    for (int pp = 0; pp < 2; pp++) {
        #pragma unroll
        for (int s = 0; s < 4; s++) {
            const float* qh = q + (size_t)(bh0 + 4 * pp + s) * (L * D);
            const float* kh = k + (size_t)(bh0 + 4 * pp + s) * (L * D);
            float*  Qb  = X + s * 3584;
            float4* KT4 = (float4*)(Qb + 1728);    // [16][29] float4
            for (int i4 = tid; i4 < 432; i4 += NT)
                ((float4*)Qb)[i4] = ((const float4*)qh)[i4];
            for (int i4 = tid; i4 < 432; i4 += NT) {
                int i  = i4 >> 4;
                int d4 = i4 & 15;
                KT4[d4 * 29 + i] = ((const float4*)kh)[i4];
            }
        }
        __syncthreads();

        const int hs  = w >> 2;                    // head slot 0..3
        const int wg  = w & 3;
        const int h   = 4 * pp + hs;
        const int r0  = wg * 7;
        const int cnt = (wg < 3) ? 7 : 6;
        const int jmax = r0 + cnt - 1;             // warp's top row
        const float* Qb  = X + hs * 3584;
        const ulonglong2* KT4 = (const ulonglong2*)(Qb + 1728);
        const int j = lane;

        u64 acc2[7] = {0ull,0ull,0ull,0ull,0ull,0ull,0ull};
        #pragma unroll
        for (int d4 = 0; d4 < 16; d4++) {
            ulonglong2 k4 = make_ulonglong2(0ull, 0ull);
            if (j <= jmax) k4 = KT4[d4 * 29 + j];
            #pragma unroll
            for (int rr = 0; rr < 7; rr++) {
                if (rr < cnt) {
                    const ulonglong2 qv =
                        *(const ulonglong2*)&Qb[(r0 + rr) * 64 + 4 * d4];
                    fma2(acc2[rr], qv.x, k4.x);
                    fma2(acc2[rr], qv.y, k4.y);
                }
            }
        }
        const float* ap = attn_pre + (size_t)(bh0 + h) * (L * L);
        #pragma unroll
        for (int rr = 0; rr < 7; rr++) {
            if (rr < cnt) {
                int i = r0 + rr;
                float lo, hi; upk2(acc2[rr], lo, hi);
                float val = 0.f;
                if (j <= i)
                    val = fmaf(0.5f, ap[i * L + j], 0.0625f * (lo + hi));
                if (j < L) A[(h * L + i) * L + j] = val;
            }
        }
        __syncthreads();
    }

    // ---------- g[p][o] = sum_c sum_{t=26-p}^{26} CW[c][t][o] (warps 0-7) ----------
    if (w < 8) {
        const int o = w;
        float hh = 0.f;
        if (lane < L) {
            #pragma unroll
            for (int c = 0; c < H; c++) hh += CW[(c * L + lane) * H + o];
        }
        #pragma unroll
        for (int off = 1; off < 32; off <<= 1) {
            float n = __shfl_up_sync(FULLMASK, hh, off);
            if (lane >= off) hh += n;
        }
        float total = __shfl_sync(FULLMASK, hh, 26);
        int   src   = 25 - lane;
        float pv    = __shfl_sync(FULLMASK, hh, src & 31);
        if (lane < L) G[lane * H + w] = total - ((src >= 0) ? pv : 0.f);
    }

    // ---------- conv (channel-split): partial Z over c-half into Z0 / Z1 ----------
    // warp w: chalf = w&1 (c in [4*chalf, 4*chalf+4)), tasks tA = 13-(w>>1),
    // tB = (w>=4) ? (w>>1)-2 : -1.  Task t covers rows p=2t(,2t+1); t=13 row 26 only.
    {
        const int  m     = lane;
        const bool mok   = (m < L);
        const int  chalf = w & 1;
        const int  c0    = chalf * 4;
        const int  tAl   = 13 - (w >> 1);
        const int  tBl   = (w >= 4) ? (w >> 1) - 2 : -1;
        float* Zh = X + chalf * 5832;

        #pragma unroll
        for (int ti = 0; ti < 2; ti++) {
            const int t = (ti == 0) ? tAl : tBl;
            if (t < 0) continue;
            const int p0 = 2 * t;
            const int np = (t == 13) ? 1 : 2;
            const int pmax = p0 + np - 1;

            u64 a0[4] = {0ull,0ull,0ull,0ull};
            u64 a1[4] = {0ull,0ull,0ull,0ull};

            for (int c = c0; c < c0 + 4; c++) {
                const float* Ac = A  + c * (L * L);
                const float* cw = CW + c * (L * H);
                u64 wp[4];
                if (np == 2) {   // weights for t-index 25-p0 (row p0+1, qq=0)
                    const ulonglong2 w0 = *(const ulonglong2*)&cw[(25 - p0) * 8];
                    const ulonglong2 w1 = *(const ulonglong2*)&cw[(25 - p0) * 8 + 4];
                    wp[0] = w0.x; wp[1] = w0.y; wp[2] = w1.x; wp[3] = w1.y;
                }
                for (int qq = 0; qq <= pmax; qq++) {
                    float x = mok ? Ac[qq * L + m] : 0.f;
                    u64 x2 = pk2(x, x);
                    u64 wc[4];
                    if (qq <= p0) {
                        const ulonglong2 w0 = *(const ulonglong2*)&cw[(26 - p0 + qq) * 8];
                        const ulonglong2 w1 = *(const ulonglong2*)&cw[(26 - p0 + qq) * 8 + 4];
                        wc[0] = w0.x; wc[1] = w0.y; wc[2] = w1.x; wc[3] = w1.y;
                        fma2(a0[0], x2, wc[0]);
                        fma2(a0[1], x2, wc[1]);
                        fma2(a0[2], x2, wc[2]);
                        fma2(a0[3], x2, wc[3]);
                    }
                    if (np == 2) {   // rotate: row p0+1 at qq uses row p0's weights from qq-1
                        fma2(a1[0], x2, wp[0]);
                        fma2(a1[1], x2, wp[1]);
                        fma2(a1[2], x2, wp[2]);
                        fma2(a1[3], x2, wp[3]);
                        wp[0] = wc[0]; wp[1] = wc[1];
                        wp[2] = wc[2]; wp[3] = wc[3];
                    }
                }
            }
            if (mok) {
                u64* zp = (u64*)(Zh + (p0 * L + m) * 8);
                *(ulonglong2*)(zp)     = make_ulonglong2(a0[0], a0[1]);
                *(ulonglong2*)(zp + 2) = make_ulonglong2(a0[2], a0[3]);
                if (np == 2) {
                    u64* zp1 = (u64*)(Zh + ((p0 + 1) * L + m) * 8);
                    *(ulonglong2*)(zp1)     = make_ulonglong2(a1[0], a1[1]);
                    *(ulonglong2*)(zp1 + 2) = make_ulonglong2(a1[2], a1[3]);
                }
            }
        }
    }
    __syncthreads();

    // ---------- pre-reduce Z = Z0 + Z1 (f32x2) ----------
    {
        u64* Z0 = (u64*)X;
        u64* Z1 = (u64*)(X + 5832);
        for (int i2 = tid; i2 < 2916; i2 += NT)
            Z0[i2] = add2(Z0[i2], Z1[i2]);
    }
    __syncthreads();

    // ---------- V prefetch heads 4..7 into X[6912..13824) (disjoint from Z reads) ----------
    {
        const float* vh0 = v + (size_t)bh0 * (L * D);
        for (int i4 = tid + 1728; i4 < 3456; i4 += NT)
            ((float4*)X)[i4] = ((const float4*)vh0)[i4];
    }

    // ---------- linear + bias-correction + relu + blend + softmax ----------
    // balanced tasks: warp w<13 -> p in {w, 25-w} (27 iters total); w==13 -> p=26
    // probs written ONLY to shared A; attn_out written vectorized afterwards.
    {
        const int j  = lane;
        const float bj = (j < L) ? BB[j] : 0.f;
        const u64 bj2 = pk2(bj, bj);
        const int pA = (w < 13) ? w : ((w == 13) ? 26 : -1);
        const int pB = (w < 13) ? 25 - w : -1;
        #pragma unroll
        for (int pi = 0; pi < 2; pi++) {
            const int p = (pi == 0) ? pA : pB;
            if (p < 0) continue;
            const ulonglong2 g01 = *(const ulonglong2*)&G[p * 8];
            const ulonglong2 g23 = *(const ulonglong2*)&G[p * 8 + 4];
            u64 acc2[4];
            acc2[0] = mul2(g01.x, bj2);
            acc2[1] = mul2(g01.y, bj2);
            acc2[2] = mul2(g23.x, bj2);
            acc2[3] = mul2(g23.y, bj2);
            const float* Zp = X + p * (L * 8);
            for (int mm = 0; mm <= p; mm++) {
                float wt = (j < L) ? WT[mm * L + j] : 0.f;
                u64 wt2 = pk2(wt, wt);
                const ulonglong2 z01 = *(const ulonglong2*)&Zp[mm * 8];
                const ulonglong2 z23 = *(const ulonglong2*)&Zp[mm * 8 + 4];
                fma2(acc2[0], wt2, z01.x);
                fma2(acc2[1], wt2, z01.y);
                fma2(acc2[2], wt2, z23.x);
                fma2(acc2[3], wt2, z23.y);
            }
            float acc[8];
            upk2(acc2[0], acc[0], acc[1]);
            upk2(acc2[1], acc[2], acc[3]);
            upk2(acc2[2], acc[4], acc[5]);
            upk2(acc2[3], acc[6], acc[7]);
            #pragma unroll
            for (int o = 0; o < H; o++) {
                float e = 0.f;
                if (j <= p) {
                    float yv = fmaxf(acc[o], 0.f);                      // relu(conv)
                    float av = A[(o * L + p) * L + j];
                    e = __expf(fmaf(0.9f, av, 0.1f * yv));              // blend
                }
                float s = e;
                #pragma unroll
                for (int off = 16; off; off >>= 1)
                    s += __shfl_xor_sync(FULLMASK, s, off);
                float pr = __fdividef(e, s);           // masked -> exact 0 (drives phase 4)
                if (j < L) A[(o * L + p) * L + j] = pr;
            }
        }
    }
    __syncthreads();

    // ---------- epilogue interval: stage V heads 0..3 + vectorized attn_out copy ----------
    // attn_out layout for batch b == A[8][27][27] flat (5832 floats, 16B aligned).
    {
        const float* vh0 = v + (size_t)bh0 * (L * D);
        for (int i4 = tid; i4 < 1728; i4 += NT)
            ((float4*)X)[i4] = ((const float4*)vh0)[i4];
        if (attn_out) {
            float4* dst = (float4*)(attn_out + (size_t)bh0 * (L * L));
            const float4* srcA = (const float4*)A;
            for (int i4 = tid; i4 < 1458; i4 += NT)
                dst[i4] = srcA[i4];
        }
    }
    __syncthreads();

    // ---------- phase 4: out = probs @ V. warp -> (head = w>>1, 32-wide d-half),
    // lane = row i; stored probs are exact 0 above the diagonal.
    {
        const int h  = w >> 1;
        const int d0 = (w & 1) * 32;
        const int i  = lane;
        const float* Vb = X + h * 1728;
        const float* Ph = A + h * (L * L);
        u64 acc2[16];
        #pragma unroll
        for (int r = 0; r < 16; r++) acc2[r] = 0ull;
        #pragma unroll 2
        for (int j = 0; j < L; j++) {
            float a = (i < L) ? Ph[i * L + j] : 0.f;   // conflict-free (stride 27)
            u64 a2 = pk2(a, a);
            const float* vr = &Vb[j * 64 + d0];
            #pragma unroll
            for (int g = 0; g < 4; g++) {
                const ulonglong2 va = *(const ulonglong2*)(vr + 8 * g);       // bcast
                fma2(acc2[4 * g + 0], a2, va.x);
                fma2(acc2[4 * g + 1], a2, va.y);
                const ulonglong2 vb = *(const ulonglong2*)(vr + 8 * g + 4);   // bcast
                fma2(acc2[4 * g + 2], a2, vb.x);
                fma2(acc2[4 * g + 3], a2, vb.y);
            }
        }
        if (i < L) {
            float* op = out + (size_t)(bh0 + h) * (L * D) + i * D + d0;
            #pragma unroll
            for (int g = 0; g < 4; g++) {
                *(ulonglong2*)(op + 8 * g)     = make_ulonglong2(acc2[4*g+0], acc2[4*g+1]);
                *(ulonglong2*)(op + 8 * g + 4) = make_ulonglong2(acc2[4*g+2], acc2[4*g+3]);
            }
        }
    }
}

extern "C" void kernel_launch(void* const* d_in, const int* in_sizes, int n_in,
                              void* d_out, int out_size) {
    const float* q  = (const float*)d_in[0];
    const float* k  = (const float*)d_in[1];
    const float* v  = (const float*)d_in[2];
    const float* ap = (const float*)d_in[3];
    // d_in[4] mask: broadcast causal triu — hardcoded, never read.
    const float* lw = (const float*)d_in[5];
    const float* lb = (const float*)d_in[6];
    const float* cw = (const float*)d_in[7];

    const int BH   = in_sizes[0] / (L * D);
    const int grid = BH / H;

    float* out = (float*)d_out;
    const size_t out_elems  = (size_t)BH * L * D;
    const size_t attn_elems = (size_t)BH * L * L;
    float* attn = ((size_t)out_size >= out_elems + attn_elems)
                      ? out + out_elems : nullptr;

    cudaFuncSetAttribute(attn2_kernel,
                         cudaFuncAttributeMaxDynamicSharedMemorySize,
                         SMEM_FLOATS * (int)sizeof(float));
    attn2_kernel<<<grid, NT, SMEM_FLOATS * sizeof(float)>>>(
        q, k, v, ap, lw, lb, cw, out, attn);
}

// round 17
// speedup vs baseline: 1.1012x; 1.1012x over previous
#include <cuda_runtime.h>
#include <cstdint>
#include <cstddef>

#define L  27
#define D  64
#define H  8
#define NT 512
#define FULLMASK 0xffffffffu

typedef unsigned long long u64;

__device__ __forceinline__ u64 pk2(float lo, float hi) {
    u64 r; asm("mov.b64 %0,{%1,%2};" : "=l"(r) : "f"(lo), "f"(hi)); return r;
}
__device__ __forceinline__ void upk2(u64 v, float& lo, float& hi) {
    asm("mov.b64 {%0,%1},%2;" : "=f"(lo), "=f"(hi) : "l"(v));
}
__device__ __forceinline__ void fma2(u64& d, u64 a, u64 b) {
    asm("fma.rn.f32x2 %0,%1,%2,%0;" : "+l"(d) : "l"(a), "l"(b));
}
__device__ __forceinline__ u64 mul2(u64 a, u64 b) {
    u64 r; asm("mul.rn.f32x2 %0,%1,%2;" : "=l"(r) : "l"(a), "l"(b)); return r;
}
__device__ __forceinline__ u64 add2(u64 a, u64 b) {
    u64 r; asm("add.rn.f32x2 %0,%1,%2;" : "=l"(r) : "l"(a), "l"(b)); return r;
}

// ---- shared memory layout (float offsets), total 22868 floats = 91472 B ----
// X region (14336 floats), time-multiplexed:
//   phase1: FOUR head slots of 3584 (Q[27][64]=1728, KT4[16][29] float4 = 1856)
//   conv  : Z0[p][m][o] at X[0..5832), Z1 at X[5832..11664)
//   linear: Z = Z0+Z1 pre-reduced into X[0..5832); V heads 4..7 staged X[6912..13824)
//   phase4: V for all 8 heads at X[0..13824)
// CW and G dedicated (CW staged once at kernel start).
#define OFF_X   0
#define OFF_A   14336                // A[8][27][27] = 5832
#define OFF_WT  (OFF_A + 5832)       // 729
#define OFF_BB  (OFF_WT + 729)       // 27
#define OFF_CW  (OFF_BB + 27)        // CW[c][t][o] = 1728 (16B aligned)
#define OFF_G   (OFF_CW + 1728)      // G[p][o] = 216
#define SMEM_FLOATS (OFF_G + 216)    // 22868

__global__ __launch_bounds__(NT, 2)
void attn2_kernel(const float* __restrict__ q, const float* __restrict__ k,
                  const float* __restrict__ v, const float* __restrict__ attn_pre,
                  const float* __restrict__ lin_w, const float* __restrict__ lin_b,
                  const float* __restrict__ conv_w,
                  float* __restrict__ out, float* __restrict__ attn_out)
{
    extern __shared__ float sm[];
    float* X  = sm + OFF_X;
    float* A  = sm + OFF_A;
    float* WT = sm + OFF_WT;
    float* BB = sm + OFF_BB;
    float* CW = sm + OFF_CW;
    float* G  = sm + OFF_G;

    const int b    = blockIdx.x;
    const int tid  = threadIdx.x;
    const int lane = tid & 31;
    const int w    = tid >> 5;       // 0..15
    const int bh0  = b * H;

    // ---------- stage linear + conv weights once, up front ----------
    for (int idx = tid; idx < L * L; idx += NT) {
        int jj = idx / L, mm = idx - jj * L;
        WT[mm * L + jj] = lin_w[idx];              // WT[m][j] = lin_w[j][m]
    }
    if (tid < L) BB[tid] = lin_b[tid];
    for (int idx = tid; idx < H * H * L; idx += NT) {
        int o = idx / (H * L);
        int r = idx - o * (H * L);
        int c = r / L, t = r - c * L;
        CW[(c * L + t) * H + o] = conv_w[idx];     // OIHW, kw==1
    }

    // ---------- phase 1: A = 0.5*attn_pre + 0.0625*QK^T (lower tri, 0 above) ----------
    // 4 heads per pass; 4 warps per head; ~7 rows per warp.
    for (int pp = 0; pp < 2; pp++) {
        #pragma unroll
        for (int s = 0; s < 4; s++) {
            const float* qh = q + (size_t)(bh0 + 4 * pp + s) * (L * D);
            const float* kh = k + (size_t)(bh0 + 4 * pp + s) * (L * D);
            float*  Qb  = X + s * 3584;
            float4* KT4 = (float4*)(Qb + 1728);    // [16][29] float4
            for (int i4 = tid; i4 < 432; i4 += NT)
                ((float4*)Qb)[i4] = ((const float4*)qh)[i4];
            for (int i4 = tid; i4 < 432; i4 += NT) {
                int i  = i4 >> 4;
                int d4 = i4 & 15;
                KT4[d4 * 29 + i] = ((const float4*)kh)[i4];
            }
        }
        __syncthreads();

        const int hs  = w >> 2;                    // head slot 0..3
        const int wg  = w & 3;
        const int h   = 4 * pp + hs;
        const int r0  = wg * 7;
        const int cnt = (wg < 3) ? 7 : 6;
        const float* Qb  = X + hs * 3584;
        const ulonglong2* KT4 = (const ulonglong2*)(Qb + 1728);
        const int j = lane;

        u64 acc2[7] = {0ull,0ull,0ull,0ull,0ull,0ull,0ull};
        #pragma unroll
        for (int d4 = 0; d4 < 16; d4++) {
            ulonglong2 k4 = make_ulonglong2(0ull, 0ull);
            if (j < L) k4 = KT4[d4 * 29 + j];
            #pragma unroll
            for (int rr = 0; rr < 7; rr++) {
                if (rr < cnt) {
                    const ulonglong2 qv =
                        *(const ulonglong2*)&Qb[(r0 + rr) * 64 + 4 * d4];
                    fma2(acc2[rr], qv.x, k4.x);
                    fma2(acc2[rr], qv.y, k4.y);
                }
            }
        }
        const float* ap = attn_pre + (size_t)(bh0 + h) * (L * L);
        #pragma unroll
        for (int rr = 0; rr < 7; rr++) {
            if (rr < cnt) {
                int i = r0 + rr;
                float lo, hi; upk2(acc2[rr], lo, hi);
                float val = 0.f;
                if (j <= i)
                    val = fmaf(0.5f, ap[i * L + j], 0.0625f * (lo + hi));
                if (j < L) A[(h * L + i) * L + j] = val;
            }
        }
        __syncthreads();
    }

    // ---------- g[p][o] = sum_c sum_{t=26-p}^{26} CW[c][t][o] (warps 0-7) ----------
    if (w < 8) {
        const int o = w;
        float hh = 0.f;
        if (lane < L) {
            #pragma unroll
            for (int c = 0; c < H; c++) hh += CW[(c * L + lane) * H + o];
        }
        #pragma unroll
        for (int off = 1; off < 32; off <<= 1) {
            float n = __shfl_up_sync(FULLMASK, hh, off);
            if (lane >= off) hh += n;
        }
        float total = __shfl_sync(FULLMASK, hh, 26);
        int   src   = 25 - lane;
        float pv    = __shfl_sync(FULLMASK, hh, src & 31);
        if (lane < L) G[lane * H + w] = total - ((src >= 0) ? pv : 0.f);
    }

    // ---------- conv (channel-split): partial Z over c-half into Z0 / Z1 ----------
    // warp w: chalf = w&1 (c in [4*chalf, 4*chalf+4)), tasks tA = 13-(w>>1),
    // tB = (w>=4) ? (w>>1)-2 : -1.  Task t covers rows p=2t(,2t+1); t=13 row 26 only.
    // Inner loop split: qq = 0..p0 unguarded (both rows), explicit tail qq = p0+1.
    {
        const int  m     = lane;
        const bool mok   = (m < L);
        const int  chalf = w & 1;
        const int  c0    = chalf * 4;
        const int  tAl   = 13 - (w >> 1);
        const int  tBl   = (w >= 4) ? (w >> 1) - 2 : -1;
        float* Zh = X + chalf * 5832;

        #pragma unroll
        for (int ti = 0; ti < 2; ti++) {
            const int t = (ti == 0) ? tAl : tBl;
            if (t < 0) continue;
            const int p0 = 2 * t;
            const int np = (t == 13) ? 1 : 2;

            u64 a0[4] = {0ull,0ull,0ull,0ull};
            u64 a1[4] = {0ull,0ull,0ull,0ull};

            for (int c = c0; c < c0 + 4; c++) {
                const float* Ac = A  + c * (L * L);
                const float* cw = CW + c * (L * H);
                u64 wp[4];
                if (np == 2) {   // weights for t-index 25-p0 (row p0+1, qq=0)
                    const ulonglong2 w0 = *(const ulonglong2*)&cw[(25 - p0) * 8];
                    const ulonglong2 w1 = *(const ulonglong2*)&cw[(25 - p0) * 8 + 4];
                    wp[0] = w0.x; wp[1] = w0.y; wp[2] = w1.x; wp[3] = w1.y;
                }
                // main body: qq = 0..p0, no predicates
                for (int qq = 0; qq <= p0; qq++) {
                    float x = mok ? Ac[qq * L + m] : 0.f;
                    u64 x2 = pk2(x, x);
                    const ulonglong2 w0 = *(const ulonglong2*)&cw[(26 - p0 + qq) * 8];
                    const ulonglong2 w1 = *(const ulonglong2*)&cw[(26 - p0 + qq) * 8 + 4];
                    fma2(a0[0], x2, w0.x);
                    fma2(a0[1], x2, w0.y);
                    fma2(a0[2], x2, w1.x);
                    fma2(a0[3], x2, w1.y);
                    if (np == 2) {   // rotate: row p0+1 at qq uses row p0's weights from qq-1
                        fma2(a1[0], x2, wp[0]);
                        fma2(a1[1], x2, wp[1]);
                        fma2(a1[2], x2, wp[2]);
                        fma2(a1[3], x2, wp[3]);
                        wp[0] = w0.x; wp[1] = w0.y;
                        wp[2] = w1.x; wp[3] = w1.y;
                    }
                }
                // tail: qq = p0+1, row p0+1 only (weights = row p0's from qq=p0)
                if (np == 2) {
                    float x = mok ? Ac[(p0 + 1) * L + m] : 0.f;
                    u64 x2 = pk2(x, x);
                    fma2(a1[0], x2, wp[0]);
                    fma2(a1[1], x2, wp[1]);
                    fma2(a1[2], x2, wp[2]);
                    fma2(a1[3], x2, wp[3]);
                }
            }
            if (mok) {
                u64* zp = (u64*)(Zh + (p0 * L + m) * 8);
                *(ulonglong2*)(zp)     = make_ulonglong2(a0[0], a0[1]);
                *(ulonglong2*)(zp + 2) = make_ulonglong2(a0[2], a0[3]);
                if (np == 2) {
                    u64* zp1 = (u64*)(Zh + ((p0 + 1) * L + m) * 8);
                    *(ulonglong2*)(zp1)     = make_ulonglong2(a1[0], a1[1]);
                    *(ulonglong2*)(zp1 + 2) = make_ulonglong2(a1[2], a1[3]);
                }
            }
        }
    }
    __syncthreads();

    // ---------- pre-reduce Z = Z0 + Z1 (f32x2) ----------
    {
        u64* Z0 = (u64*)X;
        u64* Z1 = (u64*)(X + 5832);
        for (int i2 = tid; i2 < 2916; i2 += NT)
            Z0[i2] = add2(Z0[i2], Z1[i2]);
    }
    __syncthreads();

    // ---------- V prefetch heads 4..7 into X[6912..13824) (disjoint from Z reads) ----------
    {
        const float* vh0 = v + (size_t)bh0 * (L * D);
        for (int i4 = tid + 1728; i4 < 3456; i4 += NT)
            ((float4*)X)[i4] = ((const float4*)vh0)[i4];
    }

    // ---------- linear + bias-correction + relu + blend + softmax ----------
    // balanced tasks: warp w<13 -> p in {w, 25-w} (27 iters total); w==13 -> p=26
    // probs written ONLY to shared A; attn_out written vectorized afterwards.
    {
        const int j  = lane;
        const float bj = (j < L) ? BB[j] : 0.f;
        const u64 bj2 = pk2(bj, bj);
        const int pA = (w < 13) ? w : ((w == 13) ? 26 : -1);
        const int pB = (w < 13) ? 25 - w : -1;
        #pragma unroll
        for (int pi = 0; pi < 2; pi++) {
            const int p = (pi == 0) ? pA : pB;
            if (p < 0) continue;
            const ulonglong2 g01 = *(const ulonglong2*)&G[p * 8];
            const ulonglong2 g23 = *(const ulonglong2*)&G[p * 8 + 4];
            u64 acc2[4];
            acc2[0] = mul2(g01.x, bj2);
            acc2[1] = mul2(g01.y, bj2);
            acc2[2] = mul2(g23.x, bj2);
            acc2[3] = mul2(g23.y, bj2);
            const float* Zp = X + p * (L * 8);
            for (int mm = 0; mm <= p; mm++) {
                float wt = (j < L) ? WT[mm * L + j] : 0.f;
                u64 wt2 = pk2(wt, wt);
                const ulonglong2 z01 = *(const ulonglong2*)&Zp[mm * 8];
                const ulonglong2 z23 = *(const ulonglong2*)&Zp[mm * 8 + 4];
                fma2(acc2[0], wt2, z01.x);
                fma2(acc2[1], wt2, z01.y);
                fma2(acc2[2], wt2, z23.x);
                fma2(acc2[3], wt2, z23.y);
            }
            float acc[8];
            upk2(acc2[0], acc[0], acc[1]);
            upk2(acc2[1], acc[2], acc[3]);
            upk2(acc2[2], acc[4], acc[5]);
            upk2(acc2[3], acc[6], acc[7]);
            #pragma unroll
            for (int o = 0; o < H; o++) {
                float e = 0.f;
                if (j <= p) {
                    float yv = fmaxf(acc[o], 0.f);                      // relu(conv)
                    float av = A[(o * L + p) * L + j];
                    e = __expf(fmaf(0.9f, av, 0.1f * yv));              // blend
                }
                float s = e;
                #pragma unroll
                for (int off = 16; off; off >>= 1)
                    s += __shfl_xor_sync(FULLMASK, s, off);
                float pr = __fdividef(e, s);           // masked -> exact 0 (drives phase 4)
                if (j < L) A[(o * L + p) * L + j] = pr;
            }
        }
    }
    __syncthreads();

    // ---------- epilogue interval: stage V heads 0..3 + vectorized attn_out copy ----------
    // attn_out layout for batch b == A[8][27][27] flat (5832 floats, 16B aligned).
    {
        const float* vh0 = v + (size_t)bh0 * (L * D);
        for (int i4 = tid; i4 < 1728; i4 += NT)
            ((float4*)X)[i4] = ((const float4*)vh0)[i4];
        if (attn_out) {
            float4* dst = (float4*)(attn_out + (size_t)bh0 * (L * L));
            const float4* srcA = (const float4*)A;
            for (int i4 = tid; i4 < 1458; i4 += NT)
                dst[i4] = srcA[i4];
        }
    }
    __syncthreads();

    // ---------- phase 4: out = probs @ V. warp -> (head = w>>1, 32-wide d-half),
    // lane = row i; stored probs are exact 0 above the diagonal.
    {
        const int h  = w >> 1;
        const int d0 = (w & 1) * 32;
        const int i  = lane;
        const float* Vb = X + h * 1728;
        const float* Ph = A + h * (L * L);
        u64 acc2[16];
        #pragma unroll
        for (int r = 0; r < 16; r++) acc2[r] = 0ull;
        #pragma unroll 1
        for (int j = 0; j < L; j++) {
            float a = (i < L) ? Ph[i * L + j] : 0.f;   // conflict-free (stride 27)
            u64 a2 = pk2(a, a);
            const float* vr = &Vb[j * 64 + d0];
            #pragma unroll
            for (int g = 0; g < 4; g++) {
                const ulonglong2 va = *(const ulonglong2*)(vr + 8 * g);       // bcast
                fma2(acc2[4 * g + 0], a2, va.x);
                fma2(acc2[4 * g + 1], a2, va.y);
                const ulonglong2 vb = *(const ulonglong2*)(vr + 8 * g + 4);   // bcast
                fma2(acc2[4 * g + 2], a2, vb.x);
                fma2(acc2[4 * g + 3], a2, vb.y);
            }
        }
        if (i < L) {
            float* op = out + (size_t)(bh0 + h) * (L * D) + i * D + d0;
            #pragma unroll
            for (int g = 0; g < 4; g++) {
                *(ulonglong2*)(op + 8 * g)     = make_ulonglong2(acc2[4*g+0], acc2[4*g+1]);
                *(ulonglong2*)(op + 8 * g + 4) = make_ulonglong2(acc2[4*g+2], acc2[4*g+3]);
            }
        }
    }
}

extern "C" void kernel_launch(void* const* d_in, const int* in_sizes, int n_in,
                              void* d_out, int out_size) {
    const float* q  = (const float*)d_in[0];
    const float* k  = (const float*)d_in[1];
    const float* v  = (const float*)d_in[2];
    const float* ap = (const float*)d_in[3];
    // d_in[4] mask: broadcast causal triu — hardcoded, never read.
    const float* lw = (const float*)d_in[5];
    const float* lb = (const float*)d_in[6];
    const float* cw = (const float*)d_in[7];

    const int BH   = in_sizes[0] / (L * D);
    const int grid = BH / H;

    float* out = (float*)d_out;
    const size_t out_elems  = (size_t)BH * L * D;
    const size_t attn_elems = (size_t)BH * L * L;
    float* attn = ((size_t)out_size >= out_elems + attn_elems)
                      ? out + out_elems : nullptr;

    cudaFuncSetAttribute(attn2_kernel,
                         cudaFuncAttributeMaxDynamicSharedMemorySize,
                         SMEM_FLOATS * (int)sizeof(float));
    attn2_kernel<<<grid, NT, SMEM_FLOATS * sizeof(float)>>>(
        q, k, v, ap, lw, lb, cw, out, attn);
}